// round 2
// baseline (speedup 1.0000x reference)
#include <cuda_runtime.h>
#include <math.h>

// YOLO layer, input x (64, 255, 44, 44) f32 -> out (64, 5808, 85) f32.
//   out[b, a*1936 + s, c] = f(x[b, a*85 + c, s])
//   c==0: (sig(v)+gx)*8   c==1: (sig(v)+gy)*8
//   c==2: exp(v)*aw[a]    c==3: exp(v)*ah[a]   c>=4: sig(v)
//
// Structure: 128 threads = 128 spatial positions. Each thread walks all 85
// channels (ch 0-3 peeled, 4-84 branch-free), writing smem in OUTPUT layout
// [sl][85] (stride-85 STS: gcd(85,32)=1 -> conflict-free). Write phase is a
// straight float4 smem->gmem copy. All LDG/STS offsets become immediates
// after unrolling -> minimal ALU work; kernel should be HBM-bound.

#define G44   44
#define GG    1936
#define CH    85
#define NA    3
#define TS    128            // spatial positions per block
#define NTHR  128

__constant__ float c_aw[NA] = {10.0f, 16.0f, 33.0f};   // scaled_anchor*STRIDE
__constant__ float c_ah[NA] = {13.0f, 30.0f, 23.0f};

__device__ __forceinline__ float sig_(float v) {
    return 1.0f / (1.0f + __expf(-v));
}

__global__ __launch_bounds__(NTHR)
void yolo_kernel(const float* __restrict__ x, float* __restrict__ out) {
    __shared__ float sm[TS * CH];           // 43,520 B, output layout

    const int ba = blockIdx.z;              // b*NA + a
    const int a  = ba % NA;
    const int s0 = blockIdx.x * TS;
    const int tid = threadIdx.x;

    const int valid = min(TS, GG - s0);     // 128 or 16 (last tile)

    if (tid < valid) {
        const int s  = s0 + tid;
        const int gy = s / G44;
        const int gx = s - gy * G44;

        const float* __restrict__ ib = x + (size_t)ba * CH * GG + s;  // +ch*GG
        float* __restrict__ row = sm + tid * CH;                      // +ch

        // peeled special channels
        {
            float v0 = ib[0 * GG];
            float v1 = ib[1 * GG];
            float v2 = ib[2 * GG];
            float v3 = ib[3 * GG];
            row[0] = (sig_(v0) + (float)gx) * 8.0f;
            row[1] = (sig_(v1) + (float)gy) * 8.0f;
            row[2] = __expf(v2) * c_aw[a];
            row[3] = __expf(v3) * c_ah[a];
        }

        // ch 4..84: pure sigmoid, branch-free, immediate offsets after unroll
        #pragma unroll 27
        for (int ch = 4; ch < CH; ch++) {
            row[ch] = sig_(ib[(size_t)ch * GG]);
        }
    }

    __syncthreads();

    // write phase: contiguous float4 copy smem -> gmem
    {
        const int n4 = (valid * CH) >> 2;   // valid*85 divisible by 4 (valid%4==0)
        const float4* __restrict__ sm4 = (const float4*)sm;
        float4* __restrict__ o4 =
            (float4*)(out + ((size_t)ba * GG + s0) * CH);
        #pragma unroll 6
        for (int j = tid; j < n4; j += NTHR)
            o4[j] = sm4[j];
    }
}

extern "C" void kernel_launch(void* const* d_in, const int* in_sizes, int n_in,
                              void* d_out, int out_size) {
    const float* x = (const float*)d_in[0];
    float* out = (float*)d_out;

    dim3 grid((GG + TS - 1) / TS,   // 16 spatial tiles
              1,
              64 * NA);             // 192 (b,a) matrices
    yolo_kernel<<<grid, NTHR>>>(x, out);
}

// round 3
// speedup vs baseline: 4.1075x; 4.1075x over previous
#include <cuda_runtime.h>
#include <math.h>

// YOLO layer: x (64, 255, 44, 44) f32 -> out (64, 5808, 85) f32.
//   out[b, a*1936 + s, c] = f(x[b, a*85 + c, s])
//   c==0:(sig+gx)*8  c==1:(sig+gy)*8  c==2:exp*aw  c==3:exp*ah  c>=4:sig
//
// Block = 512 thr: 128 spatial positions x 85 channels via smem transpose.
// Read: warp-per-channel, LDG.128 along s (coalesced), warp-uniform channel
//       branches, STS into output-layout smem [sl*85+ch].
// Write: contiguous float4 memcpy smem->gmem (LDS.128 + STG.128).

#define G44   44
#define GG    1936
#define CH    85
#define NA    3
#define TS    128
#define NTHR  512
#define NWARP 16

__constant__ float c_aw[NA] = {10.0f, 16.0f, 33.0f};   // scaled_anchor*STRIDE
__constant__ float c_ah[NA] = {13.0f, 30.0f, 23.0f};

__device__ __forceinline__ float sig_(float v) {
    return 1.0f / (1.0f + __expf(-v));
}

__global__ __launch_bounds__(NTHR, 4)
void yolo_kernel(const float* __restrict__ x, float* __restrict__ out) {
    __shared__ float sm[TS * CH];            // 43,520 B, output layout

    const int ba   = blockIdx.y;             // b*NA + a  (0..191)
    const int a    = ba % NA;
    const int s0   = blockIdx.x * TS;
    const int warp = threadIdx.x >> 5;
    const int lane = threadIdx.x & 31;
    const int valid = min(TS, GG - s0);      // 128, or 16 on last tile

    // ---------- read + transform: warp w covers channels w, w+16, ... ----------
    const int sl = lane << 2;                // 0..124, spatial offset in tile
    if (sl < valid) {
        const int s  = s0 + sl;
        const int gy = s / G44;
        const int gx = s - gy * G44;         // s%4==0 and 44%4==0 -> gx+3 <= 43

        const float* __restrict__ ib = x + (size_t)ba * (CH * GG) + s;
        float* __restrict__ row = sm + sl * CH;   // + k*CH + ch

        #pragma unroll 3
        for (int ch = warp; ch < CH; ch += NWARP) {
            const float4 v = *(const float4*)(ib + (size_t)ch * GG);
            float t0, t1, t2, t3;
            if (ch >= 4) {                    // warp-uniform branch
                t0 = sig_(v.x); t1 = sig_(v.y);
                t2 = sig_(v.z); t3 = sig_(v.w);
            } else if (ch == 0) {
                t0 = (sig_(v.x) + (float)(gx + 0)) * 8.0f;
                t1 = (sig_(v.y) + (float)(gx + 1)) * 8.0f;
                t2 = (sig_(v.z) + (float)(gx + 2)) * 8.0f;
                t3 = (sig_(v.w) + (float)(gx + 3)) * 8.0f;
            } else if (ch == 1) {
                const float fy = (float)gy;
                t0 = (sig_(v.x) + fy) * 8.0f;
                t1 = (sig_(v.y) + fy) * 8.0f;
                t2 = (sig_(v.z) + fy) * 8.0f;
                t3 = (sig_(v.w) + fy) * 8.0f;
            } else if (ch == 2) {
                const float aw = c_aw[a];
                t0 = __expf(v.x) * aw; t1 = __expf(v.y) * aw;
                t2 = __expf(v.z) * aw; t3 = __expf(v.w) * aw;
            } else {                          // ch == 3
                const float ah = c_ah[a];
                t0 = __expf(v.x) * ah; t1 = __expf(v.y) * ah;
                t2 = __expf(v.z) * ah; t3 = __expf(v.w) * ah;
            }
            row[0 * CH + ch] = t0;
            row[1 * CH + ch] = t1;
            row[2 * CH + ch] = t2;
            row[3 * CH + ch] = t3;
        }
    }

    __syncthreads();

    // ---------- write: contiguous float4 copy smem -> gmem ----------
    {
        const int n4 = (valid * CH) >> 2;     // valid%4==0 -> exact
        const float4* __restrict__ sm4 = (const float4*)sm;
        float4* __restrict__ o4 =
            (float4*)(out + ((size_t)ba * GG + s0) * CH);   // 16B aligned
        #pragma unroll 6
        for (int j = threadIdx.x; j < n4; j += NTHR)
            o4[j] = sm4[j];
    }
}

extern "C" void kernel_launch(void* const* d_in, const int* in_sizes, int n_in,
                              void* d_out, int out_size) {
    const float* x = (const float*)d_in[0];
    float* out = (float*)d_out;

    dim3 grid((GG + TS - 1) / TS,   // 16 spatial tiles
              64 * NA);             // 192 (b,a) matrices
    yolo_kernel<<<grid, NTHR>>>(x, out);
}

// round 4
// speedup vs baseline: 4.2653x; 1.0384x over previous
#include <cuda_runtime.h>
#include <cstdint>

// YOLO layer: x (64, 255, 44, 44) f32 -> out (64, 5808, 85) f32.
//   out[b, a*1936 + s, c] = f(x[b, a*85 + c, s])
//   c==0:(sig+gx)*8  c==1:(sig+gy)*8  c==2:exp*aw  c==3:exp*ah  c>=4:sig
//
// Read: warp-per-channel LDG.128 along s, transform, STS.32 x4 into
//       output-layout smem [sl*85+ch] (stride 85, conflict-free).
// Write: ONE cp.async.bulk (shared->global) per tile — contiguous 43,520 B.
//        Removes ~170 LDS/STG warp-instructions per tile from the issue path.

#define G44   44
#define GG    1936
#define CH    85
#define NA    3
#define TS    128
#define NTHR  512
#define NWARP 16

__constant__ float c_aw[NA] = {10.0f, 16.0f, 33.0f};   // scaled_anchor*STRIDE
__constant__ float c_ah[NA] = {13.0f, 30.0f, 23.0f};

__device__ __forceinline__ float sig_(float v) {
    return 1.0f / (1.0f + __expf(-v));
}

__global__ __launch_bounds__(NTHR, 3)
void yolo_kernel(const float* __restrict__ x, float* __restrict__ out) {
    __shared__ __align__(16) float sm[TS * CH];   // 43,520 B, output layout

    const int ba   = blockIdx.y;                  // b*NA + a (0..191)
    const int a    = ba % NA;
    const int s0   = blockIdx.x * TS;
    const int warp = threadIdx.x >> 5;
    const int lane = threadIdx.x & 31;
    const int valid = min(TS, GG - s0);           // 128, or 16 on last tile

    const int sl = lane << 2;                     // spatial offset within tile
    if (sl < valid) {
        const float* __restrict__ ib = x + (size_t)ba * (CH * GG) + (s0 + sl);
        float* __restrict__ row = sm + sl * CH;

        // ---- k = 0: channels 0..15 (special cases live only here) ----
        {
            const int ch = warp;
            const float4 v = *(const float4*)(ib + (size_t)ch * GG);
            float t0, t1, t2, t3;
            if (ch >= 4) {                        // warp-uniform
                t0 = sig_(v.x); t1 = sig_(v.y); t2 = sig_(v.z); t3 = sig_(v.w);
            } else if (ch == 0) {
                const int s  = s0 + sl;
                const int gx = s - (s / G44) * G44;   // s%4==0, 44%4==0
                t0 = (sig_(v.x) + (float)(gx + 0)) * 8.0f;
                t1 = (sig_(v.y) + (float)(gx + 1)) * 8.0f;
                t2 = (sig_(v.z) + (float)(gx + 2)) * 8.0f;
                t3 = (sig_(v.w) + (float)(gx + 3)) * 8.0f;
            } else if (ch == 1) {
                const float fy = (float)((s0 + sl) / G44);
                t0 = (sig_(v.x) + fy) * 8.0f;
                t1 = (sig_(v.y) + fy) * 8.0f;
                t2 = (sig_(v.z) + fy) * 8.0f;
                t3 = (sig_(v.w) + fy) * 8.0f;
            } else if (ch == 2) {
                const float aw = c_aw[a];
                t0 = __expf(v.x) * aw; t1 = __expf(v.y) * aw;
                t2 = __expf(v.z) * aw; t3 = __expf(v.w) * aw;
            } else {                              // ch == 3
                const float ah = c_ah[a];
                t0 = __expf(v.x) * ah; t1 = __expf(v.y) * ah;
                t2 = __expf(v.z) * ah; t3 = __expf(v.w) * ah;
            }
            row[0 * CH + ch] = t0;
            row[1 * CH + ch] = t1;
            row[2 * CH + ch] = t2;
            row[3 * CH + ch] = t3;
        }

        // ---- k = 1..5: pure sigmoid, branch-free body ----
        #pragma unroll
        for (int k = 1; k < 6; k++) {
            const int ch = warp + k * NWARP;      // 16..95
            if (ch < CH) {                        // warp-uniform predicate
                const float4 v = *(const float4*)(ib + (size_t)ch * GG);
                row[0 * CH + ch] = sig_(v.x);
                row[1 * CH + ch] = sig_(v.y);
                row[2 * CH + ch] = sig_(v.z);
                row[3 * CH + ch] = sig_(v.w);
            }
        }
    }

    __syncthreads();

    // ---- write: single bulk async copy smem -> gmem (contiguous tile) ----
    if (threadIdx.x == 0) {
        uint32_t saddr;
        asm volatile("{ .reg .u64 t; cvta.to.shared.u64 t, %1; cvt.u32.u64 %0, t; }"
                     : "=r"(saddr) : "l"(sm));
        float* gptr = out + ((size_t)ba * GG + s0) * CH;   // 16B-aligned (43520*bx)
        const uint32_t bytes = (uint32_t)(valid * CH * 4); // multiple of 16

        asm volatile("fence.proxy.async.shared::cta;" ::: "memory");
        asm volatile("cp.async.bulk.global.shared::cta.bulk_group [%0], [%1], %2;"
                     :: "l"(gptr), "r"(saddr), "r"(bytes) : "memory");
        asm volatile("cp.async.bulk.commit_group;" ::: "memory");
        asm volatile("cp.async.bulk.wait_group.read 0;" ::: "memory");
    }
}

extern "C" void kernel_launch(void* const* d_in, const int* in_sizes, int n_in,
                              void* d_out, int out_size) {
    const float* x = (const float*)d_in[0];
    float* out = (float*)d_out;

    dim3 grid((GG + TS - 1) / TS,   // 16 spatial tiles
              64 * NA);             // 192 (b,a) matrices
    yolo_kernel<<<grid, NTHR>>>(x, out);
}

// round 5
// speedup vs baseline: 5.2288x; 1.2259x over previous
#include <cuda_runtime.h>
#include <cstdint>

// YOLO layer: x (64, 255, 44, 44) f32 -> out (64, 5808, 85) f32.
//   out[b, a*1936 + s, c] = f(x[b, a*85 + c, s])
//   c==0:(sig+gx)*8  c==1:(sig+gy)*8  c==2:exp*aw  c==3:exp*ah  c>=4:sig
//
// Read: warp-per-channel LDG.128 along s, transform, STS.32 x4 into
//       output-layout smem [sl*85+ch] (stride-85: conflict-free).
// Write: ONE cp.async.bulk (shared->global) per tile, contiguous 43,520 B.
// Sigmoid: 4-instruction approx (FMUL, MUFU.EX2, FADD, MUFU.RCP) — the IEEE
// division in 1/(1+e) was ~10M warp-instructions of Newton refinement.

#define G44   44
#define GG    1936
#define CH    85
#define NA    3
#define TS    128
#define NTHR  512
#define NWARP 16

__constant__ float c_aw[NA] = {10.0f, 16.0f, 33.0f};   // scaled_anchor*STRIDE
__constant__ float c_ah[NA] = {13.0f, 30.0f, 23.0f};

__device__ __forceinline__ float sig_(float v) {
    float e;
    asm("ex2.approx.ftz.f32 %0, %1;" : "=f"(e) : "f"(v * -1.442695041f));
    float r;
    asm("rcp.approx.ftz.f32 %0, %1;" : "=f"(r) : "f"(1.0f + e));
    return r;
}

__device__ __forceinline__ float exp_(float v) {
    float e;
    asm("ex2.approx.ftz.f32 %0, %1;" : "=f"(e) : "f"(v * 1.442695041f));
    return e;
}

__global__ __launch_bounds__(NTHR, 3)
void yolo_kernel(const float* __restrict__ x, float* __restrict__ out) {
    __shared__ __align__(16) float sm[TS * CH];   // 43,520 B, output layout

    const int ba   = blockIdx.y;                  // b*NA + a (0..191)
    const int a    = ba % NA;
    const int s0   = blockIdx.x * TS;
    const int warp = threadIdx.x >> 5;
    const int lane = threadIdx.x & 31;
    const int valid = min(TS, GG - s0);           // 128, or 16 on last tile

    const int sl = lane << 2;                     // spatial offset within tile
    if (sl < valid) {
        const float* __restrict__ ib = x + (size_t)ba * (CH * GG) + (s0 + sl);
        float* __restrict__ row = sm + sl * CH;

        // ---- k = 0: channels 0..15 (special cases live only here) ----
        {
            const int ch = warp;
            const float4 v = *(const float4*)(ib + (size_t)ch * GG);
            float t0, t1, t2, t3;
            if (ch >= 4) {                        // warp-uniform
                t0 = sig_(v.x); t1 = sig_(v.y); t2 = sig_(v.z); t3 = sig_(v.w);
            } else if (ch == 0) {
                const int s  = s0 + sl;
                const int gx = s - (s / G44) * G44;   // s%4==0, 44%4==0
                t0 = (sig_(v.x) + (float)(gx + 0)) * 8.0f;
                t1 = (sig_(v.y) + (float)(gx + 1)) * 8.0f;
                t2 = (sig_(v.z) + (float)(gx + 2)) * 8.0f;
                t3 = (sig_(v.w) + (float)(gx + 3)) * 8.0f;
            } else if (ch == 1) {
                const float fy = (float)((s0 + sl) / G44);
                t0 = (sig_(v.x) + fy) * 8.0f;
                t1 = (sig_(v.y) + fy) * 8.0f;
                t2 = (sig_(v.z) + fy) * 8.0f;
                t3 = (sig_(v.w) + fy) * 8.0f;
            } else if (ch == 2) {
                const float aw = c_aw[a];
                t0 = exp_(v.x) * aw; t1 = exp_(v.y) * aw;
                t2 = exp_(v.z) * aw; t3 = exp_(v.w) * aw;
            } else {                              // ch == 3
                const float ah = c_ah[a];
                t0 = exp_(v.x) * ah; t1 = exp_(v.y) * ah;
                t2 = exp_(v.z) * ah; t3 = exp_(v.w) * ah;
            }
            row[0 * CH + ch] = t0;
            row[1 * CH + ch] = t1;
            row[2 * CH + ch] = t2;
            row[3 * CH + ch] = t3;
        }

        // ---- k = 1..5: pure sigmoid, branch-free body ----
        #pragma unroll
        for (int k = 1; k < 6; k++) {
            const int ch = warp + k * NWARP;      // 16..95
            if (ch < CH) {                        // warp-uniform predicate
                const float4 v = *(const float4*)(ib + (size_t)ch * GG);
                row[0 * CH + ch] = sig_(v.x);
                row[1 * CH + ch] = sig_(v.y);
                row[2 * CH + ch] = sig_(v.z);
                row[3 * CH + ch] = sig_(v.w);
            }
        }
    }

    __syncthreads();

    // ---- write: single bulk async copy smem -> gmem (contiguous tile) ----
    if (threadIdx.x == 0) {
        uint32_t saddr;
        asm volatile("{ .reg .u64 t; cvta.to.shared.u64 t, %1; cvt.u32.u64 %0, t; }"
                     : "=r"(saddr) : "l"(sm));
        float* gptr = out + ((size_t)ba * GG + s0) * CH;   // 16B-aligned (43520*bx)
        const uint32_t bytes = (uint32_t)(valid * CH * 4); // multiple of 16

        asm volatile("fence.proxy.async.shared::cta;" ::: "memory");
        asm volatile("cp.async.bulk.global.shared::cta.bulk_group [%0], [%1], %2;"
                     :: "l"(gptr), "r"(saddr), "r"(bytes) : "memory");
        asm volatile("cp.async.bulk.commit_group;" ::: "memory");
        asm volatile("cp.async.bulk.wait_group.read 0;" ::: "memory");
    }
}

extern "C" void kernel_launch(void* const* d_in, const int* in_sizes, int n_in,
                              void* d_out, int out_size) {
    const float* x = (const float*)d_in[0];
    float* out = (float*)d_out;

    dim3 grid((GG + TS - 1) / TS,   // 16 spatial tiles
              64 * NA);             // 192 (b,a) matrices
    yolo_kernel<<<grid, NTHR>>>(x, out);
}